// round 13
// baseline (speedup 1.0000x reference)
#include <cuda_runtime.h>
#include <math.h>

#define BB 64
#define TT 512
#define DD 512
#define II 1024
#define GG 2048                 // 4*D
#define BT (BB*TT)              // 32768

// ---------------- device scratch (static: allocation-free at run time) ------
__device__ float    g_xw1[BT * GG];
__device__ float    g_xwf[BT * GG];
__device__ float    g_xwb[BT * GG];
__device__ unsigned g_h1t[BT * DD];   // layer-1 hidden, tf32 bits (GEMM A + rec)
__device__ float    g_hf [BT * DD];   // forward hidden (float, for LN)
__device__ float    g_hb [BT * DD];   // backward hidden (float, for LN)
__device__ unsigned g_hft[BT * DD];   // tf32 shadows for rec2 exchange
__device__ unsigned g_hbt[BT * DD];

// ---------------- flag-based progress barriers -------------------------------
// 32 blocks per group, 32B-strided monotonic step counters.
__device__ unsigned g_flags1[4][256];   // layer-1: 4 batch-groups x 32 blocks
__device__ unsigned g_flags2[4][256];   // layer-2: (dir,bg) 4 groups x 32 blocks

__global__ void k_zero_flags() {
    int i = blockIdx.x * blockDim.x + threadIdx.x;
    if (i < 4 * 256) {
        g_flags1[i >> 8][i & 255] = 0;
        g_flags2[i >> 8][i & 255] = 0;
    }
}

__device__ __forceinline__ void bar_signal(unsigned* flagp, unsigned val) {
    __syncthreads();                         // all h-stores of this block done
    if (threadIdx.x == 0) {
        asm volatile("fence.acq_rel.gpu;" ::: "memory");
        asm volatile("st.relaxed.gpu.global.u32 [%0], %1;"
                     :: "l"(flagp), "r"(val) : "memory");
    }
}

// 32 arrivals: warp 0 lanes poll one producer flag each.
// Bounded tight spin, then nanosleep backoff (hang hardening).
__device__ __forceinline__ void bar_wait32(const unsigned* flags, unsigned val) {
    if (threadIdx.x < 32) {
        const unsigned* p = flags + threadIdx.x * 8;
        unsigned v;
        int spins = 0;
        for (;;) {
            asm volatile("ld.relaxed.gpu.global.u32 %0, [%1];"
                         : "=r"(v) : "l"(p));
            if (!__any_sync(0xffffffffu, (int)(v < val))) break;
            if (++spins > 4096) __nanosleep(64);
        }
        asm volatile("fence.acq_rel.gpu;" ::: "memory");
    }
    __syncthreads();
}

// ---------------- tf32 / mma / ldmatrix helpers ------------------------------
__device__ __forceinline__ unsigned f2tf(float f) {
    unsigned r; asm("cvt.rna.tf32.f32 %0, %1;" : "=r"(r) : "f"(f)); return r;
}

__device__ __forceinline__ void mma_tf32(float* d, const unsigned* a, const unsigned* b) {
    asm volatile("mma.sync.aligned.m16n8k8.row.col.f32.tf32.tf32.f32 "
        "{%0,%1,%2,%3}, {%4,%5,%6,%7}, {%8,%9}, {%0,%1,%2,%3};\n"
        : "+f"(d[0]), "+f"(d[1]), "+f"(d[2]), "+f"(d[3])
        : "r"(a[0]), "r"(a[1]), "r"(a[2]), "r"(a[3]), "r"(b[0]), "r"(b[1]));
}

__device__ __forceinline__ void ldsm4(unsigned& r0, unsigned& r1, unsigned& r2,
                                      unsigned& r3, const unsigned* p) {
    unsigned addr = (unsigned)__cvta_generic_to_shared(p);
    asm volatile("ldmatrix.sync.aligned.m8n8.x4.shared.b16 {%0,%1,%2,%3}, [%4];"
        : "=r"(r0), "=r"(r1), "=r"(r2), "=r"(r3) : "r"(addr));
}

__device__ __forceinline__ float sigm(float z) { return 1.f / (1.f + __expf(-z)); }

// ---------------- tf32 MMA GEMM: C[BT,GG] = A[BT,K] @ W[K,GG] + bias --------
// PRECONV: A already holds tf32 bit patterns (skip cvt on A path).
// A-fragments via ldmatrix (16 LDSM per chunk instead of 64 scalar LDS).
template<bool PRECONV>
__global__ void __launch_bounds__(256) k_mma_gemm(
    const float* __restrict__ A, const float* __restrict__ W,
    const float* __restrict__ bias, float* __restrict__ C, int K)
{
    __shared__ unsigned As[128][36];
    __shared__ unsigned Bs[32][136];

    const int tid  = threadIdx.x;
    const int warp = tid >> 5, lane = tid & 31;
    const int g    = lane >> 2, t = lane & 3;
    const int wm   = (warp >> 2) * 64;
    const int wn   = (warp & 3) * 32;
    const int row0 = blockIdx.y * 128, col0 = blockIdx.x * 128;

    const int a_m  = tid >> 3;
    const int a_k4 = (tid & 7) * 4;
    const int b_k  = tid >> 5;
    const int b_n4 = (tid & 31) * 4;

    // ldmatrix lane addressing for A fragments
    const int lt    = lane >> 3;
    const int arow  = ((lt & 1) << 3) + (lane & 7);
    const int akadd = (lt >> 1) << 2;

    float acc[4][4][4];
#pragma unroll
    for (int mi = 0; mi < 4; mi++)
#pragma unroll
        for (int ni = 0; ni < 4; ni++)
#pragma unroll
            for (int r = 0; r < 4; r++) acc[mi][ni][r] = 0.f;

    const float* Ap = A + (size_t)(row0 + a_m) * K + a_k4;
    const float* Wp = W + (size_t)b_k * GG + col0 + b_n4;

    float4 av[4], bv[4];
#pragma unroll
    for (int i = 0; i < 4; i++) av[i] = *(const float4*)(Ap + (size_t)(i * 32) * K);
#pragma unroll
    for (int i = 0; i < 4; i++) bv[i] = *(const float4*)(Wp + (size_t)(i * 8) * GG);

    for (int k0 = 0; k0 < K; k0 += 32) {
        __syncthreads();
#pragma unroll
        for (int i = 0; i < 4; i++) {
            uint4 u;
            if (PRECONV) {
                u.x = __float_as_uint(av[i].x); u.y = __float_as_uint(av[i].y);
                u.z = __float_as_uint(av[i].z); u.w = __float_as_uint(av[i].w);
            } else {
                u.x = f2tf(av[i].x); u.y = f2tf(av[i].y);
                u.z = f2tf(av[i].z); u.w = f2tf(av[i].w);
            }
            *(uint4*)&As[i * 32 + a_m][a_k4] = u;
        }
#pragma unroll
        for (int i = 0; i < 4; i++) {
            uint4 u; u.x = f2tf(bv[i].x); u.y = f2tf(bv[i].y);
                     u.z = f2tf(bv[i].z); u.w = f2tf(bv[i].w);
            *(uint4*)&Bs[i * 8 + b_k][b_n4] = u;
        }
        if (k0 + 32 < K) {
#pragma unroll
            for (int i = 0; i < 4; i++)
                av[i] = *(const float4*)(Ap + (size_t)(i * 32) * K + (k0 + 32));
#pragma unroll
            for (int i = 0; i < 4; i++)
                bv[i] = *(const float4*)(Wp + (size_t)(k0 + 32 + i * 8) * GG);
        }
        __syncthreads();

#pragma unroll
        for (int s = 0; s < 4; s++) {
            const int kk = s * 8;
            unsigned af[4][4];
#pragma unroll
            for (int mi = 0; mi < 4; mi++)
                ldsm4(af[mi][0], af[mi][1], af[mi][2], af[mi][3],
                      &As[wm + mi * 16 + arow][kk + akadd]);
            unsigned bfr[4][2];
#pragma unroll
            for (int ni = 0; ni < 4; ni++) {
                bfr[ni][0] = Bs[kk + t    ][wn + ni * 8 + g];
                bfr[ni][1] = Bs[kk + t + 4][wn + ni * 8 + g];
            }
#pragma unroll
            for (int mi = 0; mi < 4; mi++)
#pragma unroll
                for (int ni = 0; ni < 4; ni++)
                    mma_tf32(acc[mi][ni], af[mi], bfr[ni]);
        }
    }

#pragma unroll
    for (int mi = 0; mi < 4; mi++) {
        const int r0 = row0 + wm + mi * 16 + g;
#pragma unroll
        for (int ni = 0; ni < 4; ni++) {
            const int cb = col0 + wn + ni * 8 + 2 * t;
            const float b0 = bias[cb], b1 = bias[cb + 1];
            float2 v0; v0.x = acc[mi][ni][0] + b0; v0.y = acc[mi][ni][1] + b1;
            float2 v1; v1.x = acc[mi][ni][2] + b0; v1.y = acc[mi][ni][3] + b1;
            *(float2*)&C[(size_t)r0       * GG + cb] = v0;
            *(float2*)&C[(size_t)(r0 + 8) * GG + cb] = v1;
        }
    }
}

extern __shared__ unsigned dsm[];

// ---------------- layer-1 recurrence -----------------------------------------
// 128 blocks = 4 CONTIGUOUS batch-groups x 32 col-groups (die-local barriers).
// Block: 16 batches x 64 gate-cols. 8 warps K-split. U frags in REGISTERS.
#define H1W 516
#define Z1P 80
#define SMEM_REC1 (16*H1W*4 + 8*16*Z1P*4)    // 73984

__global__ void __launch_bounds__(256, 1) k_rec1(
    const float* __restrict__ xw, const float* __restrict__ U,
    unsigned* __restrict__ seqt)
{
    unsigned (*Hs)[H1W] = (unsigned(*)[H1W])dsm;
    float* zslab = (float*)(dsm + 16 * H1W);       // [8][16][Z1P]

    const int bx = blockIdx.x;
    const int bg = bx >> 5, cg = bx & 31;          // contiguous groups
    const int bbase = bg * 16, u0 = cg * 16;

    unsigned* myflag = &g_flags1[bg][cg * 8];
    const unsigned* gflags = &g_flags1[bg][0];

    const int tid  = threadIdx.x;
    const int warp = tid >> 5, lane = tid & 31;
    const int g    = lane >> 2, t = lane & 3;

    // U fragments -> registers (once)
    unsigned bfr[8][8][2];
#pragma unroll
    for (int s = 0; s < 8; s++)
#pragma unroll
        for (int ni = 0; ni < 8; ni++) {
            const int c = ni * 8 + g;
            const int gate = c >> 4, uu = c & 15;
            const size_t n = (size_t)gate * DD + u0 + uu;
            const int kg = warp * 64 + s * 8 + t;
            bfr[s][ni][0] = f2tf(U[(size_t)kg * GG + n]);
            bfr[s][ni][1] = f2tf(U[(size_t)(kg + 4) * GG + n]);
        }

    const int lt    = lane >> 3;
    const int arow  = ((lt & 1) << 3) + (lane & 7);
    const int akadd = (lt >> 1) << 2;

    const int gb = tid >> 4, guu = tid & 15;
    float c_reg = 0.f;

    // prefetch xw for step 0
    float xwv[4];
#pragma unroll
    for (int gate = 0; gate < 4; gate++)
        xwv[gate] = xw[((size_t)(bbase + gb) * TT + 0) * GG + (size_t)gate * DD + u0 + guu];

    for (int st = 0; st < TT; st++) {
        const int tout = st, tprev = st - 1;

        if (st > 0) bar_wait32(gflags, (unsigned)st);

        float acc[8][4];
#pragma unroll
        for (int ni = 0; ni < 8; ni++)
#pragma unroll
            for (int r = 0; r < 4; r++) acc[ni][r] = 0.f;

        if (tprev >= 0) {
#pragma unroll
            for (int i = 0; i < 8; i++) {
                const int e = i * 256 + tid;
                const int b = e >> 7, k4 = (e & 127) << 2;
                *(uint4*)&Hs[b][k4] =
                    *(const uint4*)&seqt[((size_t)(bbase + b) * TT + tprev) * DD + k4];
            }
            __syncthreads();

#pragma unroll
            for (int s = 0; s < 8; s++) {
                const int kk = warp * 64 + s * 8;
                unsigned af[4];
                ldsm4(af[0], af[1], af[2], af[3], &Hs[arow][kk + akadd]);
#pragma unroll
                for (int ni = 0; ni < 8; ni++)
                    mma_tf32(acc[ni], af, bfr[s][ni]);
            }
        }

        {
            float* zs = zslab + warp * 16 * Z1P;
#pragma unroll
            for (int ni = 0; ni < 8; ni++) {
                const int c = ni * 8 + 2 * t;
                float2 v0; v0.x = acc[ni][0]; v0.y = acc[ni][1];
                float2 v1; v1.x = acc[ni][2]; v1.y = acc[ni][3];
                *(float2*)&zs[(size_t)g       * Z1P + c] = v0;
                *(float2*)&zs[(size_t)(g + 8) * Z1P + c] = v1;
            }
        }
        __syncthreads();

        {
            float z[4];
#pragma unroll
            for (int gate = 0; gate < 4; gate++) {
                const int cidx = gate * 16 + guu;
                float s = 0.f;
#pragma unroll
                for (int w = 0; w < 8; w++)
                    s += zslab[((size_t)w * 16 + gb) * Z1P + cidx];
                z[gate] = s + xwv[gate];
            }
            const float si = sigm(z[0]), sf = sigm(z[1]), so = sigm(z[3]);
            const float gr = fmaxf(z[2], 0.f);
            const float cn = sf * c_reg + si * gr;
            c_reg = cn;
            const float hv = so * fmaxf(cn, 0.f);
            seqt[((size_t)(bbase + gb) * TT + tout) * DD + u0 + guu] = f2tf(hv);
        }

        if (st + 1 < TT) {
#pragma unroll
            for (int gate = 0; gate < 4; gate++)
                xwv[gate] = xw[((size_t)(bbase + gb) * TT + (st + 1)) * GG
                               + (size_t)gate * DD + u0 + guu];
        }

        if (st < TT - 1) bar_signal(myflag, (unsigned)(st + 1));
    }
}

// ---------------- layer-2 fused fwd/bwd recurrence ---------------------------
// 128 blocks: dir(2) x bg(2) x cg(32) (cg contiguous -> die-local groups).
// Block: 32 batches x 64 gate-cols. U slice in SMEM n-major; B frags via
// ldmatrix. zslab ALIASES Hs.
#define USW 516
#define Z2P 72
#define SMEM_REC2 (64*USW*4 + 8*32*Z2P*4)    // 205824

__global__ void __launch_bounds__(256, 1) k_rec2(
    const float* __restrict__ xwf, const float* __restrict__ Uf,
    float* __restrict__ hf, unsigned* __restrict__ hft,
    const float* __restrict__ xwb, const float* __restrict__ Ub,
    float* __restrict__ hb, unsigned* __restrict__ hbt)
{
    unsigned (*Us)[USW] = (unsigned(*)[USW])dsm;
    unsigned* shreg = dsm + 64 * USW;
    unsigned (*Hs)[USW] = (unsigned(*)[USW])shreg;   // [32][516]
    float* zslab = (float*)shreg;                    // [8][32][Z2P] (alias)

    const int bx  = blockIdx.x;
    const int dir = bx >> 6;
    const int bg2 = (bx >> 5) & 1, cg = bx & 31;
    const int grp = dir * 2 + bg2;
    const int bbase = bg2 * 32, u0 = cg * 16;

    unsigned* myflag = &g_flags2[grp][cg * 8];
    const unsigned* gflags = &g_flags2[grp][0];

    const float* xw = dir ? xwb : xwf;
    const float* U  = dir ? Ub  : Uf;
    float*    seq   = dir ? hb  : hf;
    unsigned* seqt  = dir ? hbt : hft;

    const int tid  = threadIdx.x;
    const int warp = tid >> 5, lane = tid & 31;
    const int g    = lane >> 2, t = lane & 3;

    for (int idx = tid; idx < 64 * 512; idx += 256) {
        const int col = idx >> 9, k = idx & 511;
        const int gate = col >> 4, uu = col & 15;
        Us[col][k] = f2tf(U[(size_t)k * GG + (size_t)gate * DD + u0 + uu]);
    }
    __syncthreads();

    const int lt    = lane >> 3;
    const int arow  = ((lt & 1) << 3) + (lane & 7);
    const int akadd = (lt >> 1) << 2;
    const int brow  = ((lt >> 1) << 3) + (lane & 7);
    const int bkadd = (lt & 1) << 2;

    const int gbb = tid >> 3, guu = tid & 7;
    float creg[2] = {0.f, 0.f};

    // prefetch xw for step 0
    float xwv[8];
    {
        const int tout0 = dir ? (TT - 1) : 0;
        const size_t xrow = ((size_t)(bbase + gbb) * TT + tout0) * GG;
#pragma unroll
        for (int ui = 0; ui < 2; ui++)
#pragma unroll
            for (int gate = 0; gate < 4; gate++)
                xwv[ui * 4 + gate] = xw[xrow + (size_t)gate * DD + u0 + guu + ui * 8];
    }

    for (int st = 0; st < TT; st++) {
        const int tout  = dir ? (TT - 1 - st) : st;
        const int tprev = (st == 0) ? -1 : (dir ? tout + 1 : tout - 1);

        if (st > 0) bar_wait32(gflags, (unsigned)st);

        float acc[2][8][4];
#pragma unroll
        for (int mi = 0; mi < 2; mi++)
#pragma unroll
            for (int ni = 0; ni < 8; ni++)
#pragma unroll
                for (int r = 0; r < 4; r++) acc[mi][ni][r] = 0.f;

        if (tprev >= 0) {
#pragma unroll
            for (int i = 0; i < 16; i++) {
                const int e = i * 256 + tid;
                const int b = e >> 7, k4 = (e & 127) << 2;
                *(uint4*)&Hs[b][k4] =
                    *(const uint4*)&seqt[((size_t)(bbase + b) * TT + tprev) * DD + k4];
            }
            __syncthreads();

#pragma unroll
            for (int s = 0; s < 8; s++) {
                const int kk = warp * 64 + s * 8;
                unsigned af[2][4];
#pragma unroll
                for (int mi = 0; mi < 2; mi++)
                    ldsm4(af[mi][0], af[mi][1], af[mi][2], af[mi][3],
                          &Hs[mi * 16 + arow][kk + akadd]);
                unsigned bfr[8][2];
#pragma unroll
                for (int np = 0; np < 4; np++) {
                    unsigned r0, r1, r2, r3;
                    ldsm4(r0, r1, r2, r3, &Us[np * 16 + brow][kk + bkadd]);
                    bfr[np * 2][0]     = r0; bfr[np * 2][1]     = r1;
                    bfr[np * 2 + 1][0] = r2; bfr[np * 2 + 1][1] = r3;
                }
#pragma unroll
                for (int mi = 0; mi < 2; mi++)
#pragma unroll
                    for (int ni = 0; ni < 8; ni++)
                        mma_tf32(acc[mi][ni], af[mi], bfr[ni]);
            }
            __syncthreads();   // all warps done reading Hs before zslab aliases
        }

        {
            float* zs = zslab + warp * 32 * Z2P;
#pragma unroll
            for (int mi = 0; mi < 2; mi++)
#pragma unroll
                for (int ni = 0; ni < 8; ni++) {
                    const int r = mi * 16, c = ni * 8 + 2 * t;
                    float2 v0; v0.x = acc[mi][ni][0]; v0.y = acc[mi][ni][1];
                    float2 v1; v1.x = acc[mi][ni][2]; v1.y = acc[mi][ni][3];
                    *(float2*)&zs[(size_t)(r + g)     * Z2P + c] = v0;
                    *(float2*)&zs[(size_t)(r + g + 8) * Z2P + c] = v1;
                }
        }
        __syncthreads();

#pragma unroll
        for (int ui = 0; ui < 2; ui++) {
            const int unit = guu + ui * 8;
            float z[4];
#pragma unroll
            for (int gate = 0; gate < 4; gate++) {
                const int cidx = gate * 16 + unit;
                float s = 0.f;
#pragma unroll
                for (int w = 0; w < 8; w++)
                    s += zslab[((size_t)w * 32 + gbb) * Z2P + cidx];
                z[gate] = s + xwv[ui * 4 + gate];
            }
            const float si = sigm(z[0]), sf = sigm(z[1]), so = sigm(z[3]);
            const float gr = fmaxf(z[2], 0.f);
            const float cn = sf * creg[ui] + si * gr;
            creg[ui] = cn;
            const float hv = so * fmaxf(cn, 0.f);
            const size_t idx = ((size_t)(bbase + gbb) * TT + tout) * DD + u0 + unit;
            seq [idx] = hv;
            seqt[idx] = f2tf(hv);
        }

        if (st + 1 < TT) {
            const int tnext = dir ? (TT - 2 - st) : (st + 1);
            const size_t xrow = ((size_t)(bbase + gbb) * TT + tnext) * GG;
#pragma unroll
            for (int ui = 0; ui < 2; ui++)
#pragma unroll
                for (int gate = 0; gate < 4; gate++)
                    xwv[ui * 4 + gate] = xw[xrow + (size_t)gate * DD + u0 + guu + ui * 8];
        }

        if (st < TT - 1) bar_signal(myflag, (unsigned)(st + 1));
    }
}

// ---------------- LayerNorm(concat(hf,hb)) * gamma + beta + residual --------
__global__ void __launch_bounds__(256) k_ln_residual(
    const float* __restrict__ x, const float* __restrict__ gamma,
    const float* __restrict__ beta, const float* __restrict__ hf,
    const float* __restrict__ hb, float* __restrict__ out)
{
    const int bt  = blockIdx.x;
    const int tid = threadIdx.x;
    const float* hfr = hf + (size_t)bt * DD;
    const float* hbr = hb + (size_t)bt * DD;

    float v[4];
    float s = 0.f;
#pragma unroll
    for (int r = 0; r < 4; r++) {
        int i = tid + r * 256;
        float val = (i < DD) ? hfr[i] : hbr[i - DD];
        v[r] = val; s += val;
    }

    __shared__ float rbuf[8];
    __shared__ float stat[2];
    const int lane = tid & 31, w = tid >> 5;
#pragma unroll
    for (int o = 16; o; o >>= 1) s += __shfl_xor_sync(0xffffffffu, s, o);
    if (lane == 0) rbuf[w] = s;
    __syncthreads();
    if (tid == 0) {
        float tsum = 0.f;
        for (int i = 0; i < 8; i++) tsum += rbuf[i];
        stat[0] = tsum * (1.f / 1024.f);
    }
    __syncthreads();
    const float mean = stat[0];

    float s2 = 0.f;
#pragma unroll
    for (int r = 0; r < 4; r++) { float d = v[r] - mean; s2 += d * d; }
#pragma unroll
    for (int o = 16; o; o >>= 1) s2 += __shfl_xor_sync(0xffffffffu, s2, o);
    if (lane == 0) rbuf[w] = s2;
    __syncthreads();
    if (tid == 0) {
        float tsum = 0.f;
        for (int i = 0; i < 8; i++) tsum += rbuf[i];
        stat[1] = rsqrtf(tsum * (1.f / 1024.f) + 1e-6f);
    }
    __syncthreads();
    const float rstd = stat[1];

    const float* xr  = x   + (size_t)bt * II;
    float*       otr = out + (size_t)bt * II;
#pragma unroll
    for (int r = 0; r < 4; r++) {
        int i = tid + r * 256;
        otr[i] = xr[i] + (v[r] - mean) * rstd * gamma[i] + beta[i];
    }
}

// ---------------- launcher ---------------------------------------------------
extern "C" void kernel_launch(void* const* d_in, const int* in_sizes, int n_in,
                              void* d_out, int out_size)
{
    (void)in_sizes; (void)n_in; (void)out_size;
    const float* x     = (const float*)d_in[0];
    const float* W1    = (const float*)d_in[1];
    const float* U1    = (const float*)d_in[2];
    const float* b1    = (const float*)d_in[3];
    const float* Wf    = (const float*)d_in[4];
    const float* Uf    = (const float*)d_in[5];
    const float* bf    = (const float*)d_in[6];
    const float* Wb    = (const float*)d_in[7];
    const float* Ub    = (const float*)d_in[8];
    const float* bb    = (const float*)d_in[9];
    const float* gamma = (const float*)d_in[10];
    const float* beta  = (const float*)d_in[11];
    float* out = (float*)d_out;

    float *xw1, *xwf, *xwb, *hf, *hb;
    unsigned *h1t, *hft, *hbt;
    cudaGetSymbolAddress((void**)&xw1, g_xw1);
    cudaGetSymbolAddress((void**)&xwf, g_xwf);
    cudaGetSymbolAddress((void**)&xwb, g_xwb);
    cudaGetSymbolAddress((void**)&h1t, g_h1t);
    cudaGetSymbolAddress((void**)&hf,  g_hf);
    cudaGetSymbolAddress((void**)&hb,  g_hb);
    cudaGetSymbolAddress((void**)&hft, g_hft);
    cudaGetSymbolAddress((void**)&hbt, g_hbt);

    cudaFuncSetAttribute(k_rec1, cudaFuncAttributeMaxDynamicSharedMemorySize, SMEM_REC1);
    cudaFuncSetAttribute(k_rec2, cudaFuncAttributeMaxDynamicSharedMemorySize, SMEM_REC2);

    dim3 ggrid(GG / 128, BT / 128);   // (16, 256)

    k_zero_flags<<<4, 256>>>();
    k_mma_gemm<false><<<ggrid, 256>>>(x, W1, b1, xw1, II);
    k_rec1<<<128, 256, SMEM_REC1>>>(xw1, U1, h1t);
    k_mma_gemm<true><<<ggrid, 256>>>((const float*)h1t, Wf, bf, xwf, DD);
    k_mma_gemm<true><<<ggrid, 256>>>((const float*)h1t, Wb, bb, xwb, DD);
    k_rec2<<<128, 256, SMEM_REC2>>>(xwf, Uf, hf, hft, xwb, Ub, hb, hbt);
    k_ln_residual<<<BT, 256>>>(x, gamma, beta, hf, hb, out);
}

// round 16
// speedup vs baseline: 1.0014x; 1.0014x over previous
#include <cuda_runtime.h>
#include <math.h>

#define BB 64
#define TT 512
#define DD 512
#define II 1024
#define GG 2048                 // 4*D
#define BT (BB*TT)              // 32768

// ---------------- device scratch (static: allocation-free at run time) ------
__device__ float    g_xw1[BT * GG];
__device__ float    g_xwf[BT * GG];
__device__ float    g_xwb[BT * GG];
__device__ unsigned g_h1t[BT * DD];   // layer-1 hidden, tf32 bits (GEMM A + rec)
__device__ float    g_hf [BT * DD];   // forward hidden (float, for LN)
__device__ float    g_hb [BT * DD];   // backward hidden (float, for LN)
__device__ unsigned g_hft[BT * DD];   // tf32 shadows for rec2 exchange
__device__ unsigned g_hbt[BT * DD];

// ---------------- flag-based progress barriers -------------------------------
// 32 blocks per group, 32B-strided monotonic step counters.
__device__ unsigned g_flags1[4][256];   // layer-1: 4 batch-groups x 32 blocks
__device__ unsigned g_flags2[4][256];   // layer-2: (dir,bg) 4 groups x 32 blocks

__global__ void k_zero_flags() {
    int i = blockIdx.x * blockDim.x + threadIdx.x;
    if (i < 4 * 256) {
        g_flags1[i >> 8][i & 255] = 0;
        g_flags2[i >> 8][i & 255] = 0;
    }
}

__device__ __forceinline__ void bar_signal(unsigned* flagp, unsigned val) {
    __syncthreads();                         // all h-stores of this block done
    if (threadIdx.x == 0) {
        asm volatile("fence.acq_rel.gpu;" ::: "memory");
        asm volatile("st.relaxed.gpu.global.u32 [%0], %1;"
                     :: "l"(flagp), "r"(val) : "memory");
    }
}

// 32 arrivals: warp 0 lanes poll one producer flag each.
// Bounded tight spin, then nanosleep backoff (hang hardening).
__device__ __forceinline__ void bar_wait32(const unsigned* flags, unsigned val) {
    if (threadIdx.x < 32) {
        const unsigned* p = flags + threadIdx.x * 8;
        unsigned v;
        int spins = 0;
        for (;;) {
            asm volatile("ld.relaxed.gpu.global.u32 %0, [%1];"
                         : "=r"(v) : "l"(p));
            if (!__any_sync(0xffffffffu, (int)(v < val))) break;
            if (++spins > 4096) __nanosleep(64);
        }
        asm volatile("fence.acq_rel.gpu;" ::: "memory");
    }
    __syncthreads();
}

// ---------------- tf32 / mma / ldmatrix / cp.async helpers -------------------
__device__ __forceinline__ unsigned f2tf(float f) {
    unsigned r; asm("cvt.rna.tf32.f32 %0, %1;" : "=r"(r) : "f"(f)); return r;
}

__device__ __forceinline__ void mma_tf32(float* d, const unsigned* a, const unsigned* b) {
    asm volatile("mma.sync.aligned.m16n8k8.row.col.f32.tf32.tf32.f32 "
        "{%0,%1,%2,%3}, {%4,%5,%6,%7}, {%8,%9}, {%0,%1,%2,%3};\n"
        : "+f"(d[0]), "+f"(d[1]), "+f"(d[2]), "+f"(d[3])
        : "r"(a[0]), "r"(a[1]), "r"(a[2]), "r"(a[3]), "r"(b[0]), "r"(b[1]));
}

__device__ __forceinline__ void ldsm4(unsigned& r0, unsigned& r1, unsigned& r2,
                                      unsigned& r3, const unsigned* p) {
    unsigned addr = (unsigned)__cvta_generic_to_shared(p);
    asm volatile("ldmatrix.sync.aligned.m8n8.x4.shared.b16 {%0,%1,%2,%3}, [%4];"
        : "=r"(r0), "=r"(r1), "=r"(r2), "=r"(r3) : "r"(addr));
}

__device__ __forceinline__ void cp16(void* smem, const void* gmem) {
    unsigned s = (unsigned)__cvta_generic_to_shared(smem);
    asm volatile("cp.async.cg.shared.global [%0], [%1], 16;"
                 :: "r"(s), "l"(gmem) : "memory");
}
__device__ __forceinline__ void cp_commit_wait() {
    asm volatile("cp.async.commit_group;\n\tcp.async.wait_group 0;" ::: "memory");
}

__device__ __forceinline__ float sigm(float z) { return 1.f / (1.f + __expf(-z)); }

extern __shared__ unsigned dsm[];

// ---------------- tf32 MMA GEMM (double-buffered smem) -----------------------
// C[BT,GG] = A[BT,K] @ W[K,GG] + bias. 128x128 tile, k-chunk 32, 8 warps.
// PRECONV: A already holds tf32 bit patterns (skip cvt on A path).
// One __syncthreads per chunk; mma reads the other buffer.
#define SMEM_GEMM ((2*128*36 + 2*32*136) * 4)   // 71680

template<bool PRECONV>
__global__ void __launch_bounds__(256) k_mma_gemm(
    const float* __restrict__ A, const float* __restrict__ W,
    const float* __restrict__ bias, float* __restrict__ C, int K)
{
    unsigned (*As)[36]  = (unsigned(*)[36])dsm;                 // [2*128][36]
    unsigned (*Bs)[136] = (unsigned(*)[136])(dsm + 2*128*36);   // [2*32][136]

    const int tid  = threadIdx.x;
    const int warp = tid >> 5, lane = tid & 31;
    const int g    = lane >> 2, t = lane & 3;
    const int wm   = (warp >> 2) * 64;
    const int wn   = (warp & 3) * 32;
    const int row0 = blockIdx.y * 128, col0 = blockIdx.x * 128;

    const int a_m  = tid >> 3;
    const int a_k4 = (tid & 7) * 4;
    const int b_k  = tid >> 5;
    const int b_n4 = (tid & 31) * 4;

    const int lt    = lane >> 3;
    const int arow  = ((lt & 1) << 3) + (lane & 7);
    const int akadd = (lt >> 1) << 2;

    float acc[4][4][4];
#pragma unroll
    for (int mi = 0; mi < 4; mi++)
#pragma unroll
        for (int ni = 0; ni < 4; ni++)
#pragma unroll
            for (int r = 0; r < 4; r++) acc[mi][ni][r] = 0.f;

    const float* Ap = A + (size_t)(row0 + a_m) * K + a_k4;
    const float* Wp = W + (size_t)b_k * GG + col0 + b_n4;

    float4 av[4], bv[4];

    // ---- preamble: chunk0 -> buf0, prefetch chunk1 regs ----
#pragma unroll
    for (int i = 0; i < 4; i++) av[i] = *(const float4*)(Ap + (size_t)(i * 32) * K);
#pragma unroll
    for (int i = 0; i < 4; i++) bv[i] = *(const float4*)(Wp + (size_t)(i * 8) * GG);
#pragma unroll
    for (int i = 0; i < 4; i++) {
        uint4 u;
        if (PRECONV) {
            u.x = __float_as_uint(av[i].x); u.y = __float_as_uint(av[i].y);
            u.z = __float_as_uint(av[i].z); u.w = __float_as_uint(av[i].w);
        } else {
            u.x = f2tf(av[i].x); u.y = f2tf(av[i].y);
            u.z = f2tf(av[i].z); u.w = f2tf(av[i].w);
        }
        *(uint4*)&As[i * 32 + a_m][a_k4] = u;
    }
#pragma unroll
    for (int i = 0; i < 4; i++) {
        uint4 u; u.x = f2tf(bv[i].x); u.y = f2tf(bv[i].y);
                 u.z = f2tf(bv[i].z); u.w = f2tf(bv[i].w);
        *(uint4*)&Bs[i * 8 + b_k][b_n4] = u;
    }
    if (32 < K) {
#pragma unroll
        for (int i = 0; i < 4; i++)
            av[i] = *(const float4*)(Ap + (size_t)(i * 32) * K + 32);
#pragma unroll
        for (int i = 0; i < 4; i++)
            bv[i] = *(const float4*)(Wp + (size_t)(32 + i * 8) * GG);
    }
    __syncthreads();

    int p = 0;
    for (int k0 = 0; k0 < K; k0 += 32) {
        // ---- compute on buffer p ----
        unsigned (*Asp)[36]  = As + p * 128;
        unsigned (*Bsp)[136] = Bs + p * 32;
#pragma unroll
        for (int s = 0; s < 4; s++) {
            const int kk = s * 8;
            unsigned af[4][4];
#pragma unroll
            for (int mi = 0; mi < 4; mi++)
                ldsm4(af[mi][0], af[mi][1], af[mi][2], af[mi][3],
                      &Asp[wm + mi * 16 + arow][kk + akadd]);
            unsigned bfr[4][2];
#pragma unroll
            for (int ni = 0; ni < 4; ni++) {
                bfr[ni][0] = Bsp[kk + t    ][wn + ni * 8 + g];
                bfr[ni][1] = Bsp[kk + t + 4][wn + ni * 8 + g];
            }
#pragma unroll
            for (int mi = 0; mi < 4; mi++)
#pragma unroll
                for (int ni = 0; ni < 4; ni++)
                    mma_tf32(acc[mi][ni], af[mi], bfr[ni]);
        }

        if (k0 + 32 < K) {
            // store prefetched regs (chunk k0+32) into the other buffer
            const int q = 1 - p;
#pragma unroll
            for (int i = 0; i < 4; i++) {
                uint4 u;
                if (PRECONV) {
                    u.x = __float_as_uint(av[i].x); u.y = __float_as_uint(av[i].y);
                    u.z = __float_as_uint(av[i].z); u.w = __float_as_uint(av[i].w);
                } else {
                    u.x = f2tf(av[i].x); u.y = f2tf(av[i].y);
                    u.z = f2tf(av[i].z); u.w = f2tf(av[i].w);
                }
                *(uint4*)&As[q * 128 + i * 32 + a_m][a_k4] = u;
            }
#pragma unroll
            for (int i = 0; i < 4; i++) {
                uint4 u; u.x = f2tf(bv[i].x); u.y = f2tf(bv[i].y);
                         u.z = f2tf(bv[i].z); u.w = f2tf(bv[i].w);
                *(uint4*)&Bs[q * 32 + i * 8 + b_k][b_n4] = u;
            }
            if (k0 + 64 < K) {
#pragma unroll
                for (int i = 0; i < 4; i++)
                    av[i] = *(const float4*)(Ap + (size_t)(i * 32) * K + (k0 + 64));
#pragma unroll
                for (int i = 0; i < 4; i++)
                    bv[i] = *(const float4*)(Wp + (size_t)(k0 + 64 + i * 8) * GG);
            }
            __syncthreads();
            p = q;
        }
    }

#pragma unroll
    for (int mi = 0; mi < 4; mi++) {
        const int r0 = row0 + wm + mi * 16 + g;
#pragma unroll
        for (int ni = 0; ni < 4; ni++) {
            const int cb = col0 + wn + ni * 8 + 2 * t;
            const float b0 = bias[cb], b1 = bias[cb + 1];
            float2 v0; v0.x = acc[mi][ni][0] + b0; v0.y = acc[mi][ni][1] + b1;
            float2 v1; v1.x = acc[mi][ni][2] + b0; v1.y = acc[mi][ni][3] + b1;
            *(float2*)&C[(size_t)r0       * GG + cb] = v0;
            *(float2*)&C[(size_t)(r0 + 8) * GG + cb] = v1;
        }
    }
}

// ---------------- layer-1 recurrence -----------------------------------------
// 128 blocks = 4 batch-groups x 32 col-groups (INTERLEAVED mapping, R10-best).
// Block: 16 batches x 64 gate-cols. 8 warps K-split. U frags in REGISTERS.
#define H1W 516
#define Z1P 80
#define SMEM_REC1 (16*H1W*4 + 8*16*Z1P*4)    // 73984

__global__ void __launch_bounds__(256, 1) k_rec1(
    const float* __restrict__ xw, const float* __restrict__ U,
    unsigned* __restrict__ seqt)
{
    unsigned (*Hs)[H1W] = (unsigned(*)[H1W])dsm;
    float* zslab = (float*)(dsm + 16 * H1W);       // [8][16][Z1P]

    const int bx = blockIdx.x;
    const int bg = bx & 3, cg = bx >> 2;           // interleaved groups (best)
    const int bbase = bg * 16, u0 = cg * 16;

    unsigned* myflag = &g_flags1[bg][cg * 8];
    const unsigned* gflags = &g_flags1[bg][0];

    const int tid  = threadIdx.x;
    const int warp = tid >> 5, lane = tid & 31;
    const int g    = lane >> 2, t = lane & 3;

    // U fragments -> registers (once)
    unsigned bfr[8][8][2];
#pragma unroll
    for (int s = 0; s < 8; s++)
#pragma unroll
        for (int ni = 0; ni < 8; ni++) {
            const int c = ni * 8 + g;
            const int gate = c >> 4, uu = c & 15;
            const size_t n = (size_t)gate * DD + u0 + uu;
            const int kg = warp * 64 + s * 8 + t;
            bfr[s][ni][0] = f2tf(U[(size_t)kg * GG + n]);
            bfr[s][ni][1] = f2tf(U[(size_t)(kg + 4) * GG + n]);
        }

    const int lt    = lane >> 3;
    const int arow  = ((lt & 1) << 3) + (lane & 7);
    const int akadd = (lt >> 1) << 2;

    const int gb = tid >> 4, guu = tid & 15;
    float c_reg = 0.f;

    // prefetch xw for step 0
    float xwv[4];
#pragma unroll
    for (int gate = 0; gate < 4; gate++)
        xwv[gate] = xw[((size_t)(bbase + gb) * TT + 0) * GG + (size_t)gate * DD + u0 + guu];

    for (int st = 0; st < TT; st++) {
        const int tout = st, tprev = st - 1;

        if (st > 0) bar_wait32(gflags, (unsigned)st);

        float acc[8][4];
#pragma unroll
        for (int ni = 0; ni < 8; ni++)
#pragma unroll
            for (int r = 0; r < 4; r++) acc[ni][r] = 0.f;

        if (tprev >= 0) {
            // stage H[16,512] via cp.async (no reg round-trip)
#pragma unroll
            for (int i = 0; i < 8; i++) {
                const int e = i * 256 + tid;
                const int b = e >> 7, k4 = (e & 127) << 2;
                cp16(&Hs[b][k4],
                     &seqt[((size_t)(bbase + b) * TT + tprev) * DD + k4]);
            }
            cp_commit_wait();
            __syncthreads();

#pragma unroll
            for (int s = 0; s < 8; s++) {
                const int kk = warp * 64 + s * 8;
                unsigned af[4];
                ldsm4(af[0], af[1], af[2], af[3], &Hs[arow][kk + akadd]);
#pragma unroll
                for (int ni = 0; ni < 8; ni++)
                    mma_tf32(acc[ni], af, bfr[s][ni]);
            }
        }

        {
            float* zs = zslab + warp * 16 * Z1P;
#pragma unroll
            for (int ni = 0; ni < 8; ni++) {
                const int c = ni * 8 + 2 * t;
                float2 v0; v0.x = acc[ni][0]; v0.y = acc[ni][1];
                float2 v1; v1.x = acc[ni][2]; v1.y = acc[ni][3];
                *(float2*)&zs[(size_t)g       * Z1P + c] = v0;
                *(float2*)&zs[(size_t)(g + 8) * Z1P + c] = v1;
            }
        }
        __syncthreads();

        {
            float z[4];
#pragma unroll
            for (int gate = 0; gate < 4; gate++) {
                const int cidx = gate * 16 + guu;
                float s = 0.f;
#pragma unroll
                for (int w = 0; w < 8; w++)
                    s += zslab[((size_t)w * 16 + gb) * Z1P + cidx];
                z[gate] = s + xwv[gate];
            }
            const float si = sigm(z[0]), sf = sigm(z[1]), so = sigm(z[3]);
            const float gr = fmaxf(z[2], 0.f);
            const float cn = sf * c_reg + si * gr;
            c_reg = cn;
            const float hv = so * fmaxf(cn, 0.f);
            seqt[((size_t)(bbase + gb) * TT + tout) * DD + u0 + guu] = f2tf(hv);
        }

        if (st + 1 < TT) {
#pragma unroll
            for (int gate = 0; gate < 4; gate++)
                xwv[gate] = xw[((size_t)(bbase + gb) * TT + (st + 1)) * GG
                               + (size_t)gate * DD + u0 + guu];
        }

        if (st < TT - 1) bar_signal(myflag, (unsigned)(st + 1));
    }
}

// ---------------- layer-2 fused fwd/bwd recurrence ---------------------------
// 128 blocks: dir(2) x bg(2) x cg(32). Block: 32 batches x 64 gate-cols.
// U slice in SMEM n-major; B frags via ldmatrix. zslab ALIASES Hs.
#define USW 516
#define Z2P 72
#define SMEM_REC2 (64*USW*4 + 8*32*Z2P*4)    // 205824

__global__ void __launch_bounds__(256, 1) k_rec2(
    const float* __restrict__ xwf, const float* __restrict__ Uf,
    float* __restrict__ hf, unsigned* __restrict__ hft,
    const float* __restrict__ xwb, const float* __restrict__ Ub,
    float* __restrict__ hb, unsigned* __restrict__ hbt)
{
    unsigned (*Us)[USW] = (unsigned(*)[USW])dsm;
    unsigned* shreg = dsm + 64 * USW;
    unsigned (*Hs)[USW] = (unsigned(*)[USW])shreg;   // [32][516]
    float* zslab = (float*)shreg;                    // [8][32][Z2P] (alias)

    const int bx  = blockIdx.x;
    const int dir = bx >> 6;
    const int bg2 = (bx >> 5) & 1, cg = bx & 31;
    const int grp = dir * 2 + bg2;
    const int bbase = bg2 * 32, u0 = cg * 16;

    unsigned* myflag = &g_flags2[grp][cg * 8];
    const unsigned* gflags = &g_flags2[grp][0];

    const float* xw = dir ? xwb : xwf;
    const float* U  = dir ? Ub  : Uf;
    float*    seq   = dir ? hb  : hf;
    unsigned* seqt  = dir ? hbt : hft;

    const int tid  = threadIdx.x;
    const int warp = tid >> 5, lane = tid & 31;
    const int g    = lane >> 2, t = lane & 3;

    for (int idx = tid; idx < 64 * 512; idx += 256) {
        const int col = idx >> 9, k = idx & 511;
        const int gate = col >> 4, uu = col & 15;
        Us[col][k] = f2tf(U[(size_t)k * GG + (size_t)gate * DD + u0 + uu]);
    }
    __syncthreads();

    const int lt    = lane >> 3;
    const int arow  = ((lt & 1) << 3) + (lane & 7);
    const int akadd = (lt >> 1) << 2;
    const int brow  = ((lt >> 1) << 3) + (lane & 7);
    const int bkadd = (lt & 1) << 2;

    const int gbb = tid >> 3, guu = tid & 7;
    float creg[2] = {0.f, 0.f};

    // prefetch xw for step 0
    float xwv[8];
    {
        const int tout0 = dir ? (TT - 1) : 0;
        const size_t xrow = ((size_t)(bbase + gbb) * TT + tout0) * GG;
#pragma unroll
        for (int ui = 0; ui < 2; ui++)
#pragma unroll
            for (int gate = 0; gate < 4; gate++)
                xwv[ui * 4 + gate] = xw[xrow + (size_t)gate * DD + u0 + guu + ui * 8];
    }

    for (int st = 0; st < TT; st++) {
        const int tout  = dir ? (TT - 1 - st) : st;
        const int tprev = (st == 0) ? -1 : (dir ? tout + 1 : tout - 1);

        if (st > 0) bar_wait32(gflags, (unsigned)st);

        float acc[2][8][4];
#pragma unroll
        for (int mi = 0; mi < 2; mi++)
#pragma unroll
            for (int ni = 0; ni < 8; ni++)
#pragma unroll
                for (int r = 0; r < 4; r++) acc[mi][ni][r] = 0.f;

        if (tprev >= 0) {
            // stage H[32,512] via cp.async
#pragma unroll
            for (int i = 0; i < 16; i++) {
                const int e = i * 256 + tid;
                const int b = e >> 7, k4 = (e & 127) << 2;
                cp16(&Hs[b][k4],
                     &seqt[((size_t)(bbase + b) * TT + tprev) * DD + k4]);
            }
            cp_commit_wait();
            __syncthreads();

#pragma unroll
            for (int s = 0; s < 8; s++) {
                const int kk = warp * 64 + s * 8;
                unsigned af[2][4];
#pragma unroll
                for (int mi = 0; mi < 2; mi++)
                    ldsm4(af[mi][0], af[mi][1], af[mi][2], af[mi][3],
                          &Hs[mi * 16 + arow][kk + akadd]);
                unsigned bfr[8][2];
#pragma unroll
                for (int np = 0; np < 4; np++) {
                    unsigned r0, r1, r2, r3;
                    ldsm4(r0, r1, r2, r3, &Us[np * 16 + brow][kk + bkadd]);
                    bfr[np * 2][0]     = r0; bfr[np * 2][1]     = r1;
                    bfr[np * 2 + 1][0] = r2; bfr[np * 2 + 1][1] = r3;
                }
#pragma unroll
                for (int mi = 0; mi < 2; mi++)
#pragma unroll
                    for (int ni = 0; ni < 8; ni++)
                        mma_tf32(acc[mi][ni], af[mi], bfr[ni]);
            }
            __syncthreads();   // all warps done reading Hs before zslab aliases
        }

        {
            float* zs = zslab + warp * 32 * Z2P;
#pragma unroll
            for (int mi = 0; mi < 2; mi++)
#pragma unroll
                for (int ni = 0; ni < 8; ni++) {
                    const int r = mi * 16, c = ni * 8 + 2 * t;
                    float2 v0; v0.x = acc[mi][ni][0]; v0.y = acc[mi][ni][1];
                    float2 v1; v1.x = acc[mi][ni][2]; v1.y = acc[mi][ni][3];
                    *(float2*)&zs[(size_t)(r + g)     * Z2P + c] = v0;
                    *(float2*)&zs[(size_t)(r + g + 8) * Z2P + c] = v1;
                }
        }
        __syncthreads();

#pragma unroll
        for (int ui = 0; ui < 2; ui++) {
            const int unit = guu + ui * 8;
            float z[4];
#pragma unroll
            for (int gate = 0; gate < 4; gate++) {
                const int cidx = gate * 16 + unit;
                float s = 0.f;
#pragma unroll
                for (int w = 0; w < 8; w++)
                    s += zslab[((size_t)w * 32 + gbb) * Z2P + cidx];
                z[gate] = s + xwv[ui * 4 + gate];
            }
            const float si = sigm(z[0]), sf = sigm(z[1]), so = sigm(z[3]);
            const float gr = fmaxf(z[2], 0.f);
            const float cn = sf * creg[ui] + si * gr;
            creg[ui] = cn;
            const float hv = so * fmaxf(cn, 0.f);
            const size_t idx = ((size_t)(bbase + gbb) * TT + tout) * DD + u0 + unit;
            seq [idx] = hv;
            seqt[idx] = f2tf(hv);
        }

        if (st + 1 < TT) {
            const int tnext = dir ? (TT - 2 - st) : (st + 1);
            const size_t xrow = ((size_t)(bbase + gbb) * TT + tnext) * GG;
#pragma unroll
            for (int ui = 0; ui < 2; ui++)
#pragma unroll
                for (int gate = 0; gate < 4; gate++)
                    xwv[ui * 4 + gate] = xw[xrow + (size_t)gate * DD + u0 + guu + ui * 8];
        }

        if (st < TT - 1) bar_signal(myflag, (unsigned)(st + 1));
    }
}

// ---------------- LayerNorm(concat(hf,hb)) * gamma + beta + residual --------
__global__ void __launch_bounds__(256) k_ln_residual(
    const float* __restrict__ x, const float* __restrict__ gamma,
    const float* __restrict__ beta, const float* __restrict__ hf,
    const float* __restrict__ hb, float* __restrict__ out)
{
    const int bt  = blockIdx.x;
    const int tid = threadIdx.x;
    const float* hfr = hf + (size_t)bt * DD;
    const float* hbr = hb + (size_t)bt * DD;

    float v[4];
    float s = 0.f;
#pragma unroll
    for (int r = 0; r < 4; r++) {
        int i = tid + r * 256;
        float val = (i < DD) ? hfr[i] : hbr[i - DD];
        v[r] = val; s += val;
    }

    __shared__ float rbuf[8];
    __shared__ float stat[2];
    const int lane = tid & 31, w = tid >> 5;
#pragma unroll
    for (int o = 16; o; o >>= 1) s += __shfl_xor_sync(0xffffffffu, s, o);
    if (lane == 0) rbuf[w] = s;
    __syncthreads();
    if (tid == 0) {
        float tsum = 0.f;
        for (int i = 0; i < 8; i++) tsum += rbuf[i];
        stat[0] = tsum * (1.f / 1024.f);
    }
    __syncthreads();
    const float mean = stat[0];

    float s2 = 0.f;
#pragma unroll
    for (int r = 0; r < 4; r++) { float d = v[r] - mean; s2 += d * d; }
#pragma unroll
    for (int o = 16; o; o >>= 1) s2 += __shfl_xor_sync(0xffffffffu, s2, o);
    if (lane == 0) rbuf[w] = s2;
    __syncthreads();
    if (tid == 0) {
        float tsum = 0.f;
        for (int i = 0; i < 8; i++) tsum += rbuf[i];
        stat[1] = rsqrtf(tsum * (1.f / 1024.f) + 1e-6f);
    }
    __syncthreads();
    const float rstd = stat[1];

    const float* xr  = x   + (size_t)bt * II;
    float*       otr = out + (size_t)bt * II;
#pragma unroll
    for (int r = 0; r < 4; r++) {
        int i = tid + r * 256;
        otr[i] = xr[i] + (v[r] - mean) * rstd * gamma[i] + beta[i];
    }
}

// ---------------- launcher ---------------------------------------------------
extern "C" void kernel_launch(void* const* d_in, const int* in_sizes, int n_in,
                              void* d_out, int out_size)
{
    (void)in_sizes; (void)n_in; (void)out_size;
    const float* x     = (const float*)d_in[0];
    const float* W1    = (const float*)d_in[1];
    const float* U1    = (const float*)d_in[2];
    const float* b1    = (const float*)d_in[3];
    const float* Wf    = (const float*)d_in[4];
    const float* Uf    = (const float*)d_in[5];
    const float* bf    = (const float*)d_in[6];
    const float* Wb    = (const float*)d_in[7];
    const float* Ub    = (const float*)d_in[8];
    const float* bb    = (const float*)d_in[9];
    const float* gamma = (const float*)d_in[10];
    const float* beta  = (const float*)d_in[11];
    float* out = (float*)d_out;

    float *xw1, *xwf, *xwb, *hf, *hb;
    unsigned *h1t, *hft, *hbt;
    cudaGetSymbolAddress((void**)&xw1, g_xw1);
    cudaGetSymbolAddress((void**)&xwf, g_xwf);
    cudaGetSymbolAddress((void**)&xwb, g_xwb);
    cudaGetSymbolAddress((void**)&h1t, g_h1t);
    cudaGetSymbolAddress((void**)&hf,  g_hf);
    cudaGetSymbolAddress((void**)&hb,  g_hb);
    cudaGetSymbolAddress((void**)&hft, g_hft);
    cudaGetSymbolAddress((void**)&hbt, g_hbt);

    cudaFuncSetAttribute(k_mma_gemm<false>, cudaFuncAttributeMaxDynamicSharedMemorySize, SMEM_GEMM);
    cudaFuncSetAttribute(k_mma_gemm<true>,  cudaFuncAttributeMaxDynamicSharedMemorySize, SMEM_GEMM);
    cudaFuncSetAttribute(k_rec1, cudaFuncAttributeMaxDynamicSharedMemorySize, SMEM_REC1);
    cudaFuncSetAttribute(k_rec2, cudaFuncAttributeMaxDynamicSharedMemorySize, SMEM_REC2);

    dim3 ggrid(GG / 128, BT / 128);   // (16, 256)

    k_zero_flags<<<4, 256>>>();
    k_mma_gemm<false><<<ggrid, 256, SMEM_GEMM>>>(x, W1, b1, xw1, II);
    k_rec1<<<128, 256, SMEM_REC1>>>(xw1, U1, h1t);
    k_mma_gemm<true><<<ggrid, 256, SMEM_GEMM>>>((const float*)h1t, Wf, bf, xwf, DD);
    k_mma_gemm<true><<<ggrid, 256, SMEM_GEMM>>>((const float*)h1t, Wb, bb, xwb, DD);
    k_rec2<<<128, 256, SMEM_REC2>>>(xwf, Uf, hf, hft, xwb, Ub, hb, hbt);
    k_ln_residual<<<BT, 256>>>(x, gamma, beta, hf, hb, out);
}